// round 2
// baseline (speedup 1.0000x reference)
#include <cuda_runtime.h>

#define B_   4096
#define T_   168
#define P_   16
#define H_   24
#define G_   96
#define EPB  28      // batch elements per block
#define NT   168     // threads per block (24 x 7)

__device__ __forceinline__ float fsig(float v) {
    return __fdividef(1.0f, 1.0f + __expf(-v));
}
__device__ __forceinline__ float ftanh(float v) {
    float e = __expf(2.0f * v);
    return 1.0f - __fdividef(2.0f, e + 1.0f);
}

__global__ __launch_bounds__(NT, 1) void lstm_fused_kernel(
    const float* __restrict__ x,
    const float* __restrict__ Wih1, const float* __restrict__ Whh1,
    const float* __restrict__ bih1, const float* __restrict__ bhh1,
    const float* __restrict__ Wih2, const float* __restrict__ Whh2,
    const float* __restrict__ bih2, const float* __restrict__ bhh2,
    const float* __restrict__ W1,   const float* __restrict__ b1,
    const float* __restrict__ W2,   const float* __restrict__ b2,
    float* __restrict__ out)
{
    // Transposed weight layouts: s_w[k][row] -> lanes j=0..23 read consecutive
    // words (conflict-free), duplicate lanes broadcast-merge.
    __shared__ float s_wih1[P_][G_];
    __shared__ float s_whh1[H_][G_];
    __shared__ float s_wih2[H_][G_];
    __shared__ float s_whh2[H_][G_];
    __shared__ float s_h1[2][EPB][H_];   // raw layer-1 hidden state (recurrence)
    __shared__ float s_h2[2][EPB][H_];   // raw layer-2 hidden state
    __shared__ float s_h1t[EPB][H_];     // tanh(h1) = layer-2 input (also reused for tanh(h2_last))
    __shared__ float s_x[EPB][P_];       // staged x_t (reused as MLP hidden after loop)

    const int tid   = threadIdx.x;
    const int j     = tid % 24;          // hidden index owned by this thread
    const int e0    = (tid / 24) * 4;    // first of 4 local batch elements
    const int bbase = blockIdx.x * EPB;

    // ---- stage weights (transposed) ----
    for (int i = tid; i < G_ * P_; i += NT) s_wih1[i % P_][i / P_] = Wih1[i];
    for (int i = tid; i < G_ * H_; i += NT) {
        int r = i / H_, k = i % H_;
        s_whh1[k][r] = Whh1[i];
        s_wih2[k][r] = Wih2[i];
        s_whh2[k][r] = Whh2[i];
    }
    // ---- zero h-state buffer 0 ----
    for (int i = tid; i < EPB * H_; i += NT) {
        (&s_h1[0][0][0])[i] = 0.f;
        (&s_h2[0][0][0])[i] = 0.f;
    }
    // ---- stage x[t=0] ----
    for (int i = tid; i < EPB * P_; i += NT) {
        int e = i / P_, f = i % P_;
        int b = bbase + e;
        (&s_x[0][0])[i] = (b < B_) ? x[((long)b * T_) * P_ + f] : 0.f;
    }

    // fused biases (b_ih + b_hh) for this thread's 4 gate rows, both layers
    float bg1[4], bg2[4];
    #pragma unroll
    for (int g = 0; g < 4; g++) {
        bg1[g] = bih1[g * 24 + j] + bhh1[g * 24 + j];
        bg2[g] = bih2[g * 24 + j] + bhh2[g * 24 + j];
    }

    float c1[4] = {0.f, 0.f, 0.f, 0.f};
    float c2[4] = {0.f, 0.f, 0.f, 0.f};
    float h2o[4] = {0.f, 0.f, 0.f, 0.f};
    int cur = 0;

    __syncthreads();

    for (int t = 0; t < T_; t++) {
        // ---- prefetch x[t+1] into registers (hide GMEM latency) ----
        float xp0 = 0.f, xp1 = 0.f, xp2 = 0.f;
        if (t + 1 < T_) {
            {
                int e = tid / P_, f = tid % P_;
                int b = bbase + e;
                if (b < B_) xp0 = x[((long)b * T_ + (t + 1)) * P_ + f];
            }
            {
                int i1 = tid + NT;
                int e = i1 / P_, f = i1 % P_;
                int b = bbase + e;
                if (b < B_) xp1 = x[((long)b * T_ + (t + 1)) * P_ + f];
            }
            {
                int i2 = tid + 2 * NT;
                if (i2 < EPB * P_) {
                    int e = i2 / P_, f = i2 % P_;
                    int b = bbase + e;
                    if (b < B_) xp2 = x[((long)b * T_ + (t + 1)) * P_ + f];
                }
            }
        }

        float a0[4], a1[4], a2[4], a3[4];

        // ================= layer 1 =================
        #pragma unroll
        for (int p = 0; p < 4; p++) { a0[p] = bg1[0]; a1[p] = bg1[1]; a2[p] = bg1[2]; a3[p] = bg1[3]; }
        #pragma unroll
        for (int k = 0; k < P_; k++) {
            float w0 = s_wih1[k][j],      w1 = s_wih1[k][24 + j];
            float w2 = s_wih1[k][48 + j], w3 = s_wih1[k][72 + j];
            #pragma unroll
            for (int p = 0; p < 4; p++) {
                float v = s_x[e0 + p][k];
                a0[p] += w0 * v; a1[p] += w1 * v; a2[p] += w2 * v; a3[p] += w3 * v;
            }
        }
        #pragma unroll
        for (int k = 0; k < H_; k++) {
            float w0 = s_whh1[k][j],      w1 = s_whh1[k][24 + j];
            float w2 = s_whh1[k][48 + j], w3 = s_whh1[k][72 + j];
            #pragma unroll
            for (int p = 0; p < 4; p++) {
                float v = s_h1[cur][e0 + p][k];
                a0[p] += w0 * v; a1[p] += w1 * v; a2[p] += w2 * v; a3[p] += w3 * v;
            }
        }
        #pragma unroll
        for (int p = 0; p < 4; p++) {
            float iv = fsig(a0[p]), fv = fsig(a1[p]);
            float gv = ftanh(a2[p]), ov = fsig(a3[p]);
            c1[p] = fv * c1[p] + iv * gv;
            float hn = ov * ftanh(c1[p]);
            s_h1[cur ^ 1][e0 + p][j] = hn;       // raw h1 for recurrence
            s_h1t[e0 + p][j] = ftanh(hn);        // tanh(h1) = layer-2 input
        }
        __syncthreads();

        // ================= layer 2 =================
        #pragma unroll
        for (int p = 0; p < 4; p++) { a0[p] = bg2[0]; a1[p] = bg2[1]; a2[p] = bg2[2]; a3[p] = bg2[3]; }
        #pragma unroll
        for (int k = 0; k < H_; k++) {
            float w0 = s_wih2[k][j],      w1 = s_wih2[k][24 + j];
            float w2 = s_wih2[k][48 + j], w3 = s_wih2[k][72 + j];
            #pragma unroll
            for (int p = 0; p < 4; p++) {
                float v = s_h1t[e0 + p][k];
                a0[p] += w0 * v; a1[p] += w1 * v; a2[p] += w2 * v; a3[p] += w3 * v;
            }
        }
        #pragma unroll
        for (int k = 0; k < H_; k++) {
            float w0 = s_whh2[k][j],      w1 = s_whh2[k][24 + j];
            float w2 = s_whh2[k][48 + j], w3 = s_whh2[k][72 + j];
            #pragma unroll
            for (int p = 0; p < 4; p++) {
                float v = s_h2[cur][e0 + p][k];
                a0[p] += w0 * v; a1[p] += w1 * v; a2[p] += w2 * v; a3[p] += w3 * v;
            }
        }
        #pragma unroll
        for (int p = 0; p < 4; p++) {
            float iv = fsig(a0[p]), fv = fsig(a1[p]);
            float gv = ftanh(a2[p]), ov = fsig(a3[p]);
            c2[p] = fv * c2[p] + iv * gv;
            float hn = ov * ftanh(c2[p]);
            h2o[p] = hn;
            s_h2[cur ^ 1][e0 + p][j] = hn;
        }

        // commit prefetched x[t+1] (all reads of s_x finished before first barrier)
        if (t + 1 < T_) {
            (&s_x[0][0])[tid]      = xp0;
            (&s_x[0][0])[tid + NT] = xp1;
            if (tid + 2 * NT < EPB * P_) (&s_x[0][0])[tid + 2 * NT] = xp2;
        }
        __syncthreads();
        cur ^= 1;
    }

    // ---- epilogue: features = tanh(h2 at t=T-1) ----
    #pragma unroll
    for (int p = 0; p < 4; p++) s_h1t[e0 + p][j] = ftanh(h2o[p]);
    __syncthreads();

    // MLP layer 1: 24 -> 16, relu  (reuse s_x as [EPB][16] hidden buffer)
    if (j < 16) {
        #pragma unroll
        for (int p = 0; p < 4; p++) {
            int e = e0 + p;
            float acc = b1[j];
            #pragma unroll
            for (int k = 0; k < 24; k++) acc += W1[j * 24 + k] * s_h1t[e][k];
            (&s_x[0][0])[e * 16 + j] = fmaxf(acc, 0.f);
        }
    }
    __syncthreads();

    // MLP layer 2: 16 -> 24, write output (B, 24, 1)
    #pragma unroll
    for (int p = 0; p < 4; p++) {
        int e = e0 + p;
        int b = bbase + e;
        if (b < B_) {
            float acc = b2[j];
            #pragma unroll
            for (int k = 0; k < 16; k++) acc += W2[j * 16 + k] * (&s_x[0][0])[e * 16 + k];
            out[b * 24 + j] = acc;
        }
    }
}

extern "C" void kernel_launch(void* const* d_in, const int* in_sizes, int n_in,
                              void* d_out, int out_size)
{
    const float* x    = (const float*)d_in[0];
    const float* Wih1 = (const float*)d_in[1];
    const float* Whh1 = (const float*)d_in[2];
    const float* bih1 = (const float*)d_in[3];
    const float* bhh1 = (const float*)d_in[4];
    const float* Wih2 = (const float*)d_in[5];
    const float* Whh2 = (const float*)d_in[6];
    const float* bih2 = (const float*)d_in[7];
    const float* bhh2 = (const float*)d_in[8];
    const float* W1   = (const float*)d_in[9];
    const float* b1   = (const float*)d_in[10];
    const float* W2   = (const float*)d_in[11];
    const float* b2   = (const float*)d_in[12];

    int nblk = (B_ + EPB - 1) / EPB;   // 147
    lstm_fused_kernel<<<nblk, NT>>>(x, Wih1, Whh1, bih1, bhh1,
                                    Wih2, Whh2, bih2, bhh2,
                                    W1, b1, W2, b2, (float*)d_out);
}

// round 3
// speedup vs baseline: 1.0196x; 1.0196x over previous
#include <cuda_runtime.h>

#define B_   4096
#define T_   168
#define P_   16
#define H_   24
#define EPB  32          // batch elements per block
#define NT   768         // 384 layer-1 threads + 384 layer-2 threads
#define LHALF 384

typedef unsigned long long ull;

// ---- packed f32x2 helpers (ptxas won't emit FFMA2 from C++) ----
__device__ __forceinline__ ull dup2(float w) {
    ull r; unsigned u = __float_as_uint(w);
    asm("mov.b64 %0, {%1, %1};" : "=l"(r) : "r"(u));
    return r;
}
__device__ __forceinline__ void fma2(ull& a, ull v, ull w) {
    asm("fma.rn.f32x2 %0, %1, %2, %0;" : "+l"(a) : "l"(v), "l"(w));
}
__device__ __forceinline__ float lo32(ull a) { return __uint_as_float((unsigned)a); }
__device__ __forceinline__ float hi32(ull a) { return __uint_as_float((unsigned)(a >> 32)); }

__device__ __forceinline__ float fsig(float v) {
    return __fdividef(1.0f, 1.0f + __expf(-v));
}
__device__ __forceinline__ float ftanh(float v) {
    float e = __expf(2.0f * v);
    return 1.0f - __fdividef(2.0f, e + 1.0f);
}

// accumulate K rows of state (stride STRIDE floats) against register weights
template<int K, int STRIDE>
__device__ __forceinline__ void accum_seg(const float* s, int e0, const float* wr,
                                          ull& a0, ull& a1, ull& a2, ull& a3) {
    #pragma unroll
    for (int k = 0; k < K; k++) {
        ulonglong2 vA = *(const ulonglong2*)(s + k * STRIDE + e0);
        ulonglong2 vB = *(const ulonglong2*)(s + k * STRIDE + e0 + 4);
        ull wp = dup2(wr[k]);
        fma2(a0, vA.x, wp); fma2(a1, vA.y, wp);
        fma2(a2, vB.x, wp); fma2(a3, vB.y, wp);
    }
}

__device__ __forceinline__ float act_one(const float* sa, int jj, int e, float& c) {
    float vi = fsig (sa[( 0 + jj) * 33 + e]);
    float vf = fsig (sa[(24 + jj) * 33 + e]);
    float vg = ftanh(sa[(48 + jj) * 33 + e]);
    float vo = fsig (sa[(72 + jj) * 33 + e]);
    c = vf * c + vi * vg;
    return vo * ftanh(c);
}

__global__ __launch_bounds__(NT, 1) void lstm_fused_kernel(
    const float* __restrict__ x,
    const float* __restrict__ Wih1, const float* __restrict__ Whh1,
    const float* __restrict__ bih1, const float* __restrict__ bhh1,
    const float* __restrict__ Wih2, const float* __restrict__ Whh2,
    const float* __restrict__ bih2, const float* __restrict__ bhh2,
    const float* __restrict__ W1,   const float* __restrict__ b1,
    const float* __restrict__ W2,   const float* __restrict__ b2,
    float* __restrict__ out)
{
    // state layouts: [k][32] e-contiguous -> LDS.128 broadcast reads, conflict-free STS
    __shared__ __align__(16) float s_x    [16 * 36];  // x_t staged, padded rows (144B, 16B-aligned)
    __shared__ __align__(16) float s_h1raw[24 * 32];  // layer-1 recurrent h
    __shared__ __align__(16) float s_h1t  [24 * 32];  // tanh(h1) = layer-2 input; reused for features
    __shared__ __align__(16) float s_h2raw[24 * 32];  // layer-2 recurrent h
    __shared__ float s_a1[96 * 33];                   // layer-1 gate pre-activations (stride 33: conflict-free)
    __shared__ float s_a2[96 * 33];

    const int tid   = threadIdx.x;
    const int bbase = blockIdx.x * EPB;
    const bool isL1 = tid < LHALF;
    const int  u    = isL1 ? tid : tid - LHALF;
    const int  wl   = u % 96;           // gate-row index r = g*24+j == wl
    const int  e0   = (u / 96) * 8;     // first of 8 batch elems in k-loop role
    const int  e    = tid & 31;         // act-phase batch elem
    const int  j0   = u >> 5;           // act-phase hidden index (0..11), pairs j0 / j0+12

    // ---- per-thread register weights (one gate row, one layer) ----
    float wr[48];
    ull bias;
    if (isL1) {
        #pragma unroll
        for (int k = 0; k < 16; k++) wr[k] = Wih1[wl * 16 + k];
        #pragma unroll
        for (int k = 0; k < 24; k++) wr[16 + k] = Whh1[wl * 24 + k];
        #pragma unroll
        for (int k = 0; k < 8; k++) wr[40 + k] = 0.f;
        bias = dup2(bih1[wl] + bhh1[wl]);
    } else {
        #pragma unroll
        for (int k = 0; k < 24; k++) wr[k] = Wih2[wl * 24 + k];
        #pragma unroll
        for (int k = 0; k < 24; k++) wr[24 + k] = Whh2[wl * 24 + k];
        bias = dup2(bih2[wl] + bhh2[wl]);
    }

    // ---- init shared state ----
    s_h1raw[tid % 768] = 0.f;  // NT==768: each thread zeroes one slot of each
    s_h1t  [tid % 768] = 0.f;
    s_h2raw[tid % 768] = 0.f;
    if (tid < 512) {           // stage x[t=0]
        int ee = tid >> 4, f = tid & 15;
        s_x[f * 36 + ee] = x[((bbase + ee) * T_) * P_ + f];
    }
    __syncthreads();

    float ca = 0.f, cb = 0.f;  // cell state for act pairs (j0, j0+12) of this thread's layer

    // ---- pipelined main loop: layer1 handles t=tt, layer2 handles t=tt-1 ----
    for (int tt = 0; tt <= T_; tt++) {
        // prefetch x[tt+1] into a register (hidden under k-loop)
        float xp = 0.f;
        if (tt + 1 < T_ && tid < 512) {
            int ee = tid >> 4, f = tid & 15;
            xp = x[((bbase + ee) * T_ + (tt + 1)) * P_ + f];
        }

        // ================= k-loop phase =================
        if (isL1) {
            if (tt < T_) {
                ull a0 = bias, a1 = bias, a2 = bias, a3 = bias;
                accum_seg<16, 36>(s_x,     e0, wr,      a0, a1, a2, a3);
                accum_seg<24, 32>(s_h1raw, e0, wr + 16, a0, a1, a2, a3);
                int base = wl * 33 + e0;
                s_a1[base + 0] = lo32(a0); s_a1[base + 1] = hi32(a0);
                s_a1[base + 2] = lo32(a1); s_a1[base + 3] = hi32(a1);
                s_a1[base + 4] = lo32(a2); s_a1[base + 5] = hi32(a2);
                s_a1[base + 6] = lo32(a3); s_a1[base + 7] = hi32(a3);
            }
        } else {
            if (tt >= 1) {
                ull a0 = bias, a1 = bias, a2 = bias, a3 = bias;
                accum_seg<24, 32>(s_h1t,   e0, wr,      a0, a1, a2, a3);
                accum_seg<24, 32>(s_h2raw, e0, wr + 24, a0, a1, a2, a3);
                int base = wl * 33 + e0;
                s_a2[base + 0] = lo32(a0); s_a2[base + 1] = hi32(a0);
                s_a2[base + 2] = lo32(a1); s_a2[base + 3] = hi32(a1);
                s_a2[base + 4] = lo32(a2); s_a2[base + 5] = hi32(a2);
                s_a2[base + 6] = lo32(a3); s_a2[base + 7] = hi32(a3);
            }
        }
        __syncthreads();

        // ================= activation phase =================
        if (isL1) {
            if (tt < T_) {
                float h = act_one(s_a1, j0, e, ca);
                s_h1raw[j0 * 32 + e] = h;
                s_h1t  [j0 * 32 + e] = ftanh(h);
                h = act_one(s_a1, j0 + 12, e, cb);
                s_h1raw[(j0 + 12) * 32 + e] = h;
                s_h1t  [(j0 + 12) * 32 + e] = ftanh(h);
            }
        } else if (tt >= 1) {
            float h = act_one(s_a2, j0, e, ca);
            s_h2raw[j0 * 32 + e] = h;
            if (tt == T_) s_h1t[j0 * 32 + e] = ftanh(h);      // features for head
            h = act_one(s_a2, j0 + 12, e, cb);
            s_h2raw[(j0 + 12) * 32 + e] = h;
            if (tt == T_) s_h1t[(j0 + 12) * 32 + e] = ftanh(h);
        }
        // commit prefetched x (all s_x reads finished before first barrier)
        if (tt + 1 < T_ && tid < 512) {
            int ee = tid >> 4, f = tid & 15;
            s_x[f * 36 + ee] = xp;
        }
        __syncthreads();
    }

    // ---- head MLP: relu(feat @ W1.T + b1) @ W2.T + b2 ----
    if (tid < 512) {
        int uo = tid & 15, ee = tid >> 4;
        float acc = b1[uo];
        #pragma unroll
        for (int k = 0; k < 24; k++) acc += W1[uo * 24 + k] * s_h1t[k * 32 + ee];
        s_a1[ee * 16 + uo] = fmaxf(acc, 0.f);
    }
    __syncthreads();
    {
        int uu = tid % 24, ee = tid / 24;     // 24*32 == 768 == NT
        float acc = b2[uu];
        #pragma unroll
        for (int k = 0; k < 16; k++) acc += W2[uu * 16 + k] * s_a1[ee * 16 + k];
        out[(bbase + ee) * 24 + uu] = acc;
    }
}

extern "C" void kernel_launch(void* const* d_in, const int* in_sizes, int n_in,
                              void* d_out, int out_size)
{
    const float* x    = (const float*)d_in[0];
    const float* Wih1 = (const float*)d_in[1];
    const float* Whh1 = (const float*)d_in[2];
    const float* bih1 = (const float*)d_in[3];
    const float* bhh1 = (const float*)d_in[4];
    const float* Wih2 = (const float*)d_in[5];
    const float* Whh2 = (const float*)d_in[6];
    const float* bih2 = (const float*)d_in[7];
    const float* bhh2 = (const float*)d_in[8];
    const float* W1   = (const float*)d_in[9];
    const float* b1   = (const float*)d_in[10];
    const float* W2   = (const float*)d_in[11];
    const float* b2   = (const float*)d_in[12];

    lstm_fused_kernel<<<B_ / EPB, NT>>>(x, Wih1, Whh1, bih1, bhh1,
                                        Wih2, Whh2, bih2, bhh2,
                                        W1, b1, W2, b2, (float*)d_out);
}

// round 6
// speedup vs baseline: 1.6149x; 1.5839x over previous
#include <cuda_runtime.h>

#define B_   4096
#define T_   168
#define P_   16
#define EPB  32
#define NT   768
#define LHALF 384
#define AST  34          // s_a row stride (floats): even -> STS.64, 2-way conflict only

typedef unsigned long long ull;

#define BAR_SYNC(id, n)   asm volatile("bar.sync %0, %1;"   :: "r"(id), "r"(n) : "memory")
#define BAR_ARRIVE(id, n) asm volatile("bar.arrive %0, %1;" :: "r"(id), "r"(n) : "memory")

// ---- packed f32x2 helpers ----
__device__ __forceinline__ ull dup2(float w) {
    ull r; unsigned u = __float_as_uint(w);
    asm("mov.b64 %0, {%1, %1};" : "=l"(r) : "r"(u));
    return r;
}
__device__ __forceinline__ void fma2(ull& a, ull v, ull w) {
    asm("fma.rn.f32x2 %0, %1, %2, %0;" : "+l"(a) : "l"(v), "l"(w));
}

__device__ __forceinline__ float fsig(float v) {
    return __fdividef(1.0f, 1.0f + __expf(-v));
}
__device__ __forceinline__ float ftanh(float v) {
    float e = __expf(2.0f * v);
    return 1.0f - __fdividef(2.0f, e + 1.0f);
}

template<int K, int STRIDE>
__device__ __forceinline__ void accum_seg(const float* s, int e0, const float* wr,
                                          ull& a0, ull& a1, ull& a2, ull& a3) {
    #pragma unroll
    for (int k = 0; k < K; k++) {
        ulonglong2 vA = *(const ulonglong2*)(s + k * STRIDE + e0);
        ulonglong2 vB = *(const ulonglong2*)(s + k * STRIDE + e0 + 4);
        ull wp = dup2(wr[k]);
        fma2(a0, vA.x, wp); fma2(a1, vA.y, wp);
        fma2(a2, vB.x, wp); fma2(a3, vB.y, wp);
    }
}

__device__ __forceinline__ float act_one(const float* sa, int jj, int e, float& c) {
    float vi = fsig (sa[( 0 + jj) * AST + e]);
    float vf = fsig (sa[(24 + jj) * AST + e]);
    float vg = ftanh(sa[(48 + jj) * AST + e]);
    float vo = fsig (sa[(72 + jj) * AST + e]);
    c = vf * c + vi * vg;
    return vo * ftanh(c);
}

__device__ __forceinline__ void store_gates(float* sa, int base,
                                            ull a0, ull a1, ull a2, ull a3) {
    *(ull*)(sa + base + 0) = a0;
    *(ull*)(sa + base + 2) = a1;
    *(ull*)(sa + base + 4) = a2;
    *(ull*)(sa + base + 6) = a3;
}

__global__ __launch_bounds__(NT, 1) void lstm_fused_kernel(
    const float* __restrict__ x,
    const float* __restrict__ Wih1, const float* __restrict__ Whh1,
    const float* __restrict__ bih1, const float* __restrict__ bhh1,
    const float* __restrict__ Wih2, const float* __restrict__ Whh2,
    const float* __restrict__ bih2, const float* __restrict__ bhh2,
    const float* __restrict__ W1,   const float* __restrict__ b1,
    const float* __restrict__ W2,   const float* __restrict__ b2,
    float* __restrict__ out)
{
    __shared__ __align__(16) float s_x    [16 * 36];
    __shared__ __align__(16) float s_h1raw[24 * 32];     // L1-private recurrent h
    __shared__ __align__(16) float s_h1t  [2][24 * 32];  // double-buffered handoff L1->L2
    __shared__ __align__(16) float s_h2raw[24 * 32];     // L2-private recurrent h
    __shared__ __align__(16) float s_feat [24 * 32];     // tanh(h2[T-1]) for head
    __shared__ __align__(8)  float s_a1[96 * AST];       // L1 gate pre-activations
    __shared__ __align__(8)  float s_a2[96 * AST];       // L2 gate pre-activations

    const int tid   = threadIdx.x;
    const int bbase = blockIdx.x * EPB;
    const bool isL1 = tid < LHALF;
    const int  u    = isL1 ? tid : tid - LHALF;
    const int  wl   = u % 96;           // gate-row r = g*24+j
    const int  e0   = (u / 96) * 8;     // k-loop batch-elem base (8 per thread)
    const int  e    = u & 31;           // act-phase batch elem
    const int  j0   = u >> 5;           // act-phase hidden index pair (j0, j0+12)

    // ---- init state + stage x[0] ----
    s_h1raw[tid & 767] = 0.f;           // 24*32 == 768 == NT
    s_h2raw[tid & 767] = 0.f;
    if (tid < 512) {
        int ee = tid >> 4, f = tid & 15;
        s_x[f * 36 + ee] = x[((bbase + ee) * T_) * P_ + f];
    }

    // ---- per-thread register weights ----
    float wr[48];
    ull bias;
    if (isL1) {
        #pragma unroll
        for (int k = 0; k < 16; k++) wr[k] = Wih1[wl * 16 + k];
        #pragma unroll
        for (int k = 0; k < 24; k++) wr[16 + k] = Whh1[wl * 24 + k];
        bias = dup2(bih1[wl] + bhh1[wl]);
    } else {
        #pragma unroll
        for (int k = 0; k < 24; k++) wr[k] = Wih2[wl * 24 + k];
        #pragma unroll
        for (int k = 0; k < 24; k++) wr[24 + k] = Whh2[wl * 24 + k];
        bias = dup2(bih2[wl] + bhh2[wl]);
    }
    __syncthreads();

    float ca = 0.f, cb = 0.f;

    if (isL1) {
        // ======== layer-1 group: 12 warps, own barrier domain ========
        for (int t = 0; t < T_; t++) {
            // prefetch x[t+1]
            float xp0 = 0.f, xp1 = 0.f;
            if (t + 1 < T_) {
                xp0 = x[((bbase + (tid >> 4)) * T_ + (t + 1)) * P_ + (tid & 15)];
                if (tid < 128) {
                    int i2 = tid + 384;
                    xp1 = x[((bbase + (i2 >> 4)) * T_ + (t + 1)) * P_ + (i2 & 15)];
                }
            }
            // k-loop: gates(t) from x(t), h1(t-1)
            ull a0 = bias, a1 = bias, a2 = bias, a3 = bias;
            accum_seg<16, 36>(s_x,     e0, wr,      a0, a1, a2, a3);
            accum_seg<24, 32>(s_h1raw, e0, wr + 16, a0, a1, a2, a3);
            store_gates(s_a1, wl * AST + e0, a0, a1, a2, a3);
            BAR_SYNC(2, 384);
            // make sure L2 has finished reading buffer (t&1) from step t-2
            if (t >= 2) BAR_SYNC(5 + 2 * (t & 1), 768);
            // activation
            float* buf = s_h1t[t & 1];
            float h = act_one(s_a1, j0, e, ca);
            s_h1raw[j0 * 32 + e] = h;  buf[j0 * 32 + e] = ftanh(h);
            h = act_one(s_a1, j0 + 12, e, cb);
            s_h1raw[(j0 + 12) * 32 + e] = h;  buf[(j0 + 12) * 32 + e] = ftanh(h);
            // commit x prefetch (s_x reads all done at BAR 2)
            if (t + 1 < T_) {
                s_x[(tid & 15) * 36 + (tid >> 4)] = xp0;
                if (tid < 128) { int i2 = tid + 384; s_x[(i2 & 15) * 36 + (i2 >> 4)] = xp1; }
            }
            BAR_ARRIVE(4 + 2 * (t & 1), 768);   // h1t buffer (t&1) ready for L2
            BAR_SYNC(3, 384);
        }
    } else {
        // ======== layer-2 group: 12 warps, phase-shifted ========
        for (int t = 0; t < T_; t++) {
            BAR_SYNC(4 + 2 * (t & 1), 768);     // wait h1t(t) ready
            ull a0 = bias, a1 = bias, a2 = bias, a3 = bias;
            accum_seg<24, 32>(s_h1t[t & 1], e0, wr,      a0, a1, a2, a3);
            accum_seg<24, 32>(s_h2raw,      e0, wr + 24, a0, a1, a2, a3);
            BAR_ARRIVE(5 + 2 * (t & 1), 768);   // h1t buffer (t&1) free for L1
            store_gates(s_a2, wl * AST + e0, a0, a1, a2, a3);
            BAR_SYNC(8, 384);
            float h = act_one(s_a2, j0, e, ca);
            s_h2raw[j0 * 32 + e] = h;
            if (t == T_ - 1) s_feat[j0 * 32 + e] = ftanh(h);
            h = act_one(s_a2, j0 + 12, e, cb);
            s_h2raw[(j0 + 12) * 32 + e] = h;
            if (t == T_ - 1) s_feat[(j0 + 12) * 32 + e] = ftanh(h);
            BAR_SYNC(9, 384);
        }
    }
    __syncthreads();

    // ---- head MLP: relu(feat @ W1.T + b1) @ W2.T + b2 ----
    if (tid < 512) {
        int uo = tid & 15, ee = tid >> 4;
        float acc = b1[uo];
        #pragma unroll
        for (int k = 0; k < 24; k++) acc += W1[uo * 24 + k] * s_feat[k * 32 + ee];
        s_a1[ee * 16 + uo] = fmaxf(acc, 0.f);
    }
    __syncthreads();
    {
        int uu = tid % 24, ee = tid / 24;       // 24*32 == 768
        float acc = b2[uu];
        #pragma unroll
        for (int k = 0; k < 16; k++) acc += W2[uu * 16 + k] * s_a1[ee * 16 + k];
        out[(bbase + ee) * 24 + uu] = acc;
    }
}

extern "C" void kernel_launch(void* const* d_in, const int* in_sizes, int n_in,
                              void* d_out, int out_size)
{
    const float* x    = (const float*)d_in[0];
    const float* Wih1 = (const float*)d_in[1];
    const float* Whh1 = (const float*)d_in[2];
    const float* bih1 = (const float*)d_in[3];
    const float* bhh1 = (const float*)d_in[4];
    const float* Wih2 = (const float*)d_in[5];
    const float* Whh2 = (const float*)d_in[6];
    const float* bih2 = (const float*)d_in[7];
    const float* bhh2 = (const float*)d_in[8];
    const float* W1   = (const float*)d_in[9];
    const float* b1   = (const float*)d_in[10];
    const float* W2   = (const float*)d_in[11];
    const float* b2   = (const float*)d_in[12];

    lstm_fused_kernel<<<B_ / EPB, NT>>>(x, Wih1, Whh1, bih1, bhh1,
                                        Wih2, Whh2, bih2, bhh2,
                                        W1, b1, W2, b2, (float*)d_out);
}